// round 10
// baseline (speedup 1.0000x reference)
#include <cuda_runtime.h>
#include <cuda_fp16.h>
#include <cstdint>

#define NN 512
#define TT 32
#define DD 1024
#define HH 1024
#define GG 4096   // 4*H
#define KK 3072   // H + H + D

// ---------------- scratch (device globals; no allocation allowed) -------------
__device__ float g_c[NN * HH];
__device__ float g_v[(size_t)NN * GG];
__device__ __align__(256) __half g_vxh[(size_t)NN * TT * GG];  // precomputed x@Wx + b (fp16)
__device__ __align__(256) __half g_hh[NN * HH];       // h (fp16)
__device__ __align__(256) __half g_ah[NN * HH];       // attn (fp16)
__device__ __align__(256) __half g_xh[(size_t)NN * TT * DD];   // x (fp16)
__device__ __align__(256) __half g_Ah[(size_t)NN * HH * 16];   // A (fp16)
__device__ __align__(256) __half g_wt[(size_t)GG * KK];        // W^T fp16 [4096][3072]

// ---------------- small helpers ------------------------------------------------
__device__ __forceinline__ uint32_t smem_u32(const void* p) {
    uint32_t a;
    asm("{ .reg .u64 t; cvta.to.shared.u64 t, %1; cvt.u32.u64 %0, t; }" : "=r"(a) : "l"(p));
    return a;
}
__device__ __forceinline__ void cp16(uint32_t dst, const void* src) {
    asm volatile("cp.async.cg.shared.global [%0], [%1], 16;" :: "r"(dst), "l"(src));
}
__device__ __forceinline__ void cp_commit() { asm volatile("cp.async.commit_group;" ::: "memory"); }
template <int N> __device__ __forceinline__ void cp_wait() {
    asm volatile("cp.async.wait_group %0;" :: "n"(N) : "memory");
}
__device__ __forceinline__ void ldsm4(uint32_t& r0, uint32_t& r1, uint32_t& r2, uint32_t& r3,
                                      uint32_t addr) {
    asm volatile("ldmatrix.sync.aligned.m8n8.x4.shared.b16 {%0,%1,%2,%3}, [%4];"
                 : "=r"(r0), "=r"(r1), "=r"(r2), "=r"(r3) : "r"(addr));
}
__device__ __forceinline__ void mma16816(float* d, const uint32_t* a, uint32_t b0, uint32_t b1) {
    asm volatile(
        "mma.sync.aligned.m16n8k16.row.col.f32.f16.f16.f32 "
        "{%0,%1,%2,%3}, {%4,%5,%6,%7}, {%8,%9}, {%0,%1,%2,%3};"
        : "+f"(d[0]), "+f"(d[1]), "+f"(d[2]), "+f"(d[3])
        : "r"(a[0]), "r"(a[1]), "r"(a[2]), "r"(a[3]), "r"(b0), "r"(b1));
}

// ---------------- one-time prep kernels ----------------------------------------
__global__ void prep_w(const float* __restrict__ Wx, const float* __restrict__ Wh,
                       const float* __restrict__ Wattn) {
    __shared__ float tile[32][33];
    int k0 = blockIdx.x * 32, n0 = blockIdx.y * 32;
#pragma unroll
    for (int dy = 0; dy < 32; dy += 8) {
        int k = k0 + threadIdx.y + dy;
        int n = n0 + threadIdx.x;
        const float* W;
        int kk = k;
        if (k < 1024)       { W = Wh; }
        else if (k < 2048)  { W = Wattn; kk = k - 1024; }
        else                { W = Wx;    kk = k - 2048; }
        tile[threadIdx.y + dy][threadIdx.x] = W[(size_t)kk * GG + n];
    }
    __syncthreads();
#pragma unroll
    for (int dy = 0; dy < 32; dy += 8) {
        int n = n0 + threadIdx.y + dy;
        int k = k0 + threadIdx.x;
        g_wt[(size_t)n * KK + k] = __float2half(tile[threadIdx.x][threadIdx.y + dy]);
    }
}

__global__ void cvt_x(const float* __restrict__ src) {
    size_t i = (size_t)blockIdx.x * 256 + threadIdx.x;
    float4 f = ((const float4*)src)[i];
    union { uint2 u; __half2 h[2]; } U;
    U.h[0] = __floats2half2_rn(f.x, f.y);
    U.h[1] = __floats2half2_rn(f.z, f.w);
    ((uint2*)g_xh)[i] = U.u;
}
__global__ void cvt_A(const float* __restrict__ src) {
    size_t i = (size_t)blockIdx.x * 256 + threadIdx.x;
    float4 f = ((const float4*)src)[i];
    union { uint2 u; __half2 h[2]; } U;
    U.h[0] = __floats2half2_rn(f.x, f.y);
    U.h[1] = __floats2half2_rn(f.z, f.w);
    ((uint2*)g_Ah)[i] = U.u;
}

// ---------------- init: h0 = c0 = mean over the 16 spatial cells ---------------
__global__ void init_kernel(const float* __restrict__ A) {
    int idx = blockIdx.x * 256 + threadIdx.x;
    const float4* a4 = (const float4*)(A + (size_t)idx * 16);
    float4 a0 = a4[0], a1 = a4[1], a2 = a4[2], a3 = a4[3];
    float s = ((a0.x + a0.y) + (a0.z + a0.w)) + ((a1.x + a1.y) + (a1.z + a1.w))
            + ((a2.x + a2.y) + (a2.z + a2.w)) + ((a3.x + a3.y) + (a3.z + a3.w));
    s *= (1.0f / 16.0f);
    g_c[idx] = s;
    g_hh[idx] = __float2half(s);
}

// ---------------- common attention tail (block = one n, 4 j per thread) --------
// Inputs: hv[4] (h values for j = tid*4+u), ar[4] (A rows), writes g_ah.
union ARow { uint4 u[2]; __half2 h[8]; };

__device__ __forceinline__ void attn_tail(int n, int tid, const float hv[4], const ARow ar[4]) {
    float part[16];
#pragma unroll
    for (int k = 0; k < 16; ++k) part[k] = 0.0f;
#pragma unroll
    for (int r = 0; r < 4; ++r) {
#pragma unroll
        for (int q = 0; q < 8; ++q) {
            float2 f = __half22float2(ar[r].h[q]);
            part[2 * q]     += hv[r] * f.x;
            part[2 * q + 1] += hv[r] * f.y;
        }
    }
#pragma unroll
    for (int k = 0; k < 16; ++k)
#pragma unroll
        for (int off = 16; off; off >>= 1)
            part[k] += __shfl_xor_sync(0xffffffffu, part[k], off);

    __shared__ float sred[8][16];
    __shared__ float sM[16];
    int warp = tid >> 5, lane = tid & 31;
    if (lane == 0) {
#pragma unroll
        for (int k = 0; k < 16; ++k) sred[warp][k] = part[k];
    }
    __syncthreads();

    if (tid < 32) {
        int k = lane & 15;
        float s = 0.0f;
#pragma unroll
        for (int w = 0; w < 8; ++w) s += sred[w][k];
        s *= (1.0f / 32.0f);                         // / sqrt(H)
        float m = s;
#pragma unroll
        for (int off = 8; off; off >>= 1) m = fmaxf(m, __shfl_xor_sync(0xffffffffu, m, off));
        float e = expf(s - m);
        float sum = e;
#pragma unroll
        for (int off = 8; off; off >>= 1) sum += __shfl_xor_sync(0xffffffffu, sum, off);
        if (lane < 16) sM[lane] = e / sum;
    }
    __syncthreads();

    union { uint2 u; __half2 h[2]; } O;
    float ov[4];
#pragma unroll
    for (int r = 0; r < 4; ++r) {
        float s = 0.0f;
#pragma unroll
        for (int q = 0; q < 8; ++q) {
            float2 f = __half22float2(ar[r].h[q]);
            s += f.x * sM[2 * q] + f.y * sM[2 * q + 1];
        }
        ov[r] = s;
    }
    O.h[0] = __floats2half2_rn(ov[0], ov[1]);
    O.h[1] = __floats2half2_rn(ov[2], ov[3]);
    *(uint2*)&g_ah[(size_t)n * HH + tid * 4] = O.u;
}

// ---------------- initial attention from h0 (reads g_hh) -----------------------
__global__ __launch_bounds__(256) void attn_kernel() {
    int n = blockIdx.x;
    int tid = threadIdx.x;
    const __half* Af = g_Ah + (size_t)n * HH * 16;
    ARow ar[4];
    float hv[4];
    union { uint2 u; __half2 h[2]; } Hv;
    Hv.u = *(const uint2*)&g_hh[(size_t)n * HH + tid * 4];
#pragma unroll
    for (int r = 0; r < 4; ++r) {
        int j = tid * 4 + r;
        ar[r].u[0] = *(const uint4*)(Af + (size_t)j * 16);
        ar[r].u[1] = *(const uint4*)(Af + (size_t)j * 16 + 8);
    }
    float2 h01 = __half22float2(Hv.h[0]), h23 = __half22float2(Hv.h[1]);
    hv[0] = h01.x; hv[1] = h01.y; hv[2] = h23.x; hv[3] = h23.y;
    attn_tail(n, tid, hv, ar);
}

// ---------------- fused gates + state update + output + next-step attn ---------
__global__ __launch_bounds__(256) void gate_attn(float* __restrict__ out, int t, int do_attn) {
    int n = blockIdx.x;
    int tid = threadIdx.x;
    int j0 = tid * 4;
    const float* vr   = g_v + (size_t)n * GG;
    const __half* vxr = g_vxh + ((size_t)n * TT + t) * GG;

    float4 vi4 = *(const float4*)&vr[j0];
    float4 vf4 = *(const float4*)&vr[j0 + 1024];
    float4 vo4 = *(const float4*)&vr[j0 + 2048];
    float4 vg4 = *(const float4*)&vr[j0 + 3072];
    union H4 { uint2 u; __half2 h[2]; };
    H4 xi, xf, xo, xg;
    xi.u = *(const uint2*)&vxr[j0];
    xf.u = *(const uint2*)&vxr[j0 + 1024];
    xo.u = *(const uint2*)&vxr[j0 + 2048];
    xg.u = *(const uint2*)&vxr[j0 + 3072];

    size_t cidx = (size_t)n * HH + j0;
    float4 c4 = *(const float4*)&g_c[cidx];

    float vi[4] = { vi4.x, vi4.y, vi4.z, vi4.w };
    float vf[4] = { vf4.x, vf4.y, vf4.z, vf4.w };
    float vo[4] = { vo4.x, vo4.y, vo4.z, vo4.w };
    float vg[4] = { vg4.x, vg4.y, vg4.z, vg4.w };
    float xiv[4], xfv[4], xov[4], xgv[4];
    {
        float2 a, b;
        a = __half22float2(xi.h[0]); b = __half22float2(xi.h[1]);
        xiv[0] = a.x; xiv[1] = a.y; xiv[2] = b.x; xiv[3] = b.y;
        a = __half22float2(xf.h[0]); b = __half22float2(xf.h[1]);
        xfv[0] = a.x; xfv[1] = a.y; xfv[2] = b.x; xfv[3] = b.y;
        a = __half22float2(xo.h[0]); b = __half22float2(xo.h[1]);
        xov[0] = a.x; xov[1] = a.y; xov[2] = b.x; xov[3] = b.y;
        a = __half22float2(xg.h[0]); b = __half22float2(xg.h[1]);
        xgv[0] = a.x; xgv[1] = a.y; xgv[2] = b.x; xgv[3] = b.y;
    }
    float cv[4] = { c4.x, c4.y, c4.z, c4.w };
    float hv[4];
#pragma unroll
    for (int u = 0; u < 4; ++u) {
        float ig = 1.0f / (1.0f + expf(-(vi[u] + xiv[u])));
        float fg = 1.0f / (1.0f + expf(-(vf[u] + xfv[u])));
        float og = 1.0f / (1.0f + expf(-(vo[u] + xov[u])));
        float gg = tanhf(vg[u] + xgv[u]);
        float c = fg * cv[u] + ig * gg;
        cv[u] = c;
        hv[u] = og * tanhf(c);
    }
    *(float4*)&g_c[cidx] = make_float4(cv[0], cv[1], cv[2], cv[3]);
    union { uint2 u; __half2 h[2]; } Hh;
    Hh.h[0] = __floats2half2_rn(hv[0], hv[1]);
    Hh.h[1] = __floats2half2_rn(hv[2], hv[3]);
    *(uint2*)&g_hh[cidx] = Hh.u;
    *(float4*)&out[(size_t)n * (TT * HH) + (size_t)t * HH + j0] =
        make_float4(hv[0], hv[1], hv[2], hv[3]);

    if (!do_attn) return;

    const __half* Af = g_Ah + (size_t)n * HH * 16;
    ARow ar[4];
#pragma unroll
    for (int r = 0; r < 4; ++r) {
        int j = j0 + r;
        ar[r].u[0] = *(const uint4*)(Af + (size_t)j * 16);
        ar[r].u[1] = *(const uint4*)(Af + (size_t)j * 16 + 8);
    }
    attn_tail(n, tid, hv, ar);
}

// ---------------- shared GEMM machinery (fp16 1-pass, K=128 per stage) ----------
#define STAGE_BYTES 65536
#define A_S0 0
#define A_S1 16384
#define B_S0 32768
#define B_S1 49152
#define GEMM_SMEM (3 * STAGE_BYTES)

struct WarpCtx {
    uint32_t swb, aRow, aHalf, bRow, bHalf;
};
__device__ __forceinline__ WarpCtx warp_ctx(int wm, int wn, int lane) {
    WarpCtx c;
    c.swb   = (lane & 7) << 4;
    c.aRow  = (uint32_t)(wm * 32 + (lane & 15)) * 128;
    c.aHalf = (uint32_t)(lane >> 4);
    c.bRow  = (uint32_t)(wn * 64 + (lane & 7) + ((lane >> 4) << 3)) * 128;
    c.bHalf = (uint32_t)((lane >> 3) & 1);
    return c;
}

__device__ __forceinline__ void mma_slab(float acc[2][8][4], uint32_t a_base, uint32_t b_base,
                                         const WarpCtx& c) {
#pragma unroll
    for (int q = 0; q < 4; ++q) {
        uint32_t aChunk = ((2 * q + c.aHalf) << 4) ^ c.swb;
        uint32_t bChunk = ((2 * q + c.bHalf) << 4) ^ c.swb;
        uint32_t af[2][4];
#pragma unroll
        for (int i = 0; i < 2; ++i) {
            uint32_t ao = c.aRow + (uint32_t)i * 2048 + aChunk;
            ldsm4(af[i][0], af[i][1], af[i][2], af[i][3], a_base + ao);
        }
        uint32_t bf[4][4];
#pragma unroll
        for (int p = 0; p < 4; ++p) {
            uint32_t bo = c.bRow + (uint32_t)p * 2048 + bChunk;
            ldsm4(bf[p][0], bf[p][1], bf[p][2], bf[p][3], b_base + bo);
        }
#pragma unroll
        for (int i = 0; i < 2; ++i)
#pragma unroll
            for (int g = 0; g < 8; ++g) {
                mma16816(acc[i][g], af[i],
                         bf[g >> 1][(g & 1) * 2], bf[g >> 1][(g & 1) * 2 + 1]);
            }
    }
}

// ---------------- per-step GEMM: v = [h | attn] @ [Wh; Wattn]^T  (K=2048) -------
#define NKT_S 16   // 16 stages x K128
__global__ __launch_bounds__(256, 1) void gemm_step() {
    extern __shared__ char dynsmem[];
    uint32_t sb = smem_u32(dynsmem);
    const int tid = threadIdx.x;
    const int wid = tid >> 5, lane = tid & 31;
    const WarpCtx wc = warp_ctx(wid & 3, wid >> 2, lane);
    const int m0 = blockIdx.y * 128;
    const int n0 = blockIdx.x * 128;

    float acc[2][8][4];
#pragma unroll
    for (int i = 0; i < 2; ++i)
#pragma unroll
        for (int g = 0; g < 8; ++g)
#pragma unroll
            for (int r = 0; r < 4; ++r) acc[i][g][r] = 0.0f;

    auto load_tile = [&](int kt, int stage) {   // kt indexes K128 chunks
        uint32_t base = sb + stage * STAGE_BYTES;
        const __half* ap = (kt < 8) ? g_hh : g_ah;
        size_t akoff = (size_t)(kt & 7) * 128;
        size_t bkoff = (size_t)kt * 128;
#pragma unroll
        for (int slab = 0; slab < 2; ++slab) {
            uint32_t abase = base + (slab ? A_S1 : A_S0);
            uint32_t bbase = base + (slab ? B_S1 : B_S0);
            size_t ks = (size_t)slab * 64;
#pragma unroll
            for (int i = 0; i < 4; ++i) {
                int cidx = tid + i * 256;
                int row = cidx >> 3, c16 = cidx & 7;
                uint32_t off = row * 128 + c16 * 16;
                uint32_t sw = off ^ ((off >> 3) & 0x70);
                size_t aoff = (size_t)(m0 + row) * HH + akoff + ks + (size_t)c16 * 8;
                size_t boff = (size_t)(n0 + row) * KK + bkoff + ks + (size_t)c16 * 8;
                cp16(abase + sw, ap + aoff);
                cp16(bbase + sw, g_wt + boff);
            }
        }
    };

    load_tile(0, 0); cp_commit();
    load_tile(1, 1); cp_commit();

    for (int kt = 0; kt < NKT_S; ++kt) {
        cp_wait<1>();
        __syncthreads();                 // stage kt ready AND stage (kt+2)%3 free
        if (kt + 2 < NKT_S) load_tile(kt + 2, (kt + 2) % 3);
        cp_commit();
        uint32_t base = sb + (kt % 3) * STAGE_BYTES;
        mma_slab(acc, base + A_S0, base + B_S0, wc);
        mma_slab(acc, base + A_S1, base + B_S1, wc);
    }

#pragma unroll
    for (int i = 0; i < 2; ++i) {
        int row0 = m0 + (wid & 3) * 32 + i * 16 + (lane >> 2);
#pragma unroll
        for (int g = 0; g < 8; ++g) {
            int col = n0 + (wid >> 2) * 64 + g * 8 + (lane & 3) * 2;
            *(float2*)&g_v[(size_t)row0 * GG + col]       = make_float2(acc[i][g][0], acc[i][g][1]);
            *(float2*)&g_v[(size_t)(row0 + 8) * GG + col] = make_float2(acc[i][g][2], acc[i][g][3]);
        }
    }
}

// ---------------- one-time GEMM: vx = X @ Wx^T + b  (M=16384, K=1024) -----------
#define NKT_X 8    // 8 stages x K128
__global__ __launch_bounds__(256, 1) void gemm_x(const float* __restrict__ b) {
    extern __shared__ char dynsmem[];
    uint32_t sb = smem_u32(dynsmem);
    const int tid = threadIdx.x;
    const int wid = tid >> 5, lane = tid & 31;
    const WarpCtx wc = warp_ctx(wid & 3, wid >> 2, lane);
    const int m0 = blockIdx.y * 128;
    const int n0 = blockIdx.x * 128;

    float acc[2][8][4];
#pragma unroll
    for (int i = 0; i < 2; ++i)
#pragma unroll
        for (int g = 0; g < 8; ++g)
#pragma unroll
            for (int r = 0; r < 4; ++r) acc[i][g][r] = 0.0f;

    auto load_tile = [&](int kt, int stage) {
        uint32_t base = sb + stage * STAGE_BYTES;
        size_t akoff = (size_t)kt * 128;
        size_t bkoff = 2048 + (size_t)kt * 128;
#pragma unroll
        for (int slab = 0; slab < 2; ++slab) {
            uint32_t abase = base + (slab ? A_S1 : A_S0);
            uint32_t bbase = base + (slab ? B_S1 : B_S0);
            size_t ks = (size_t)slab * 64;
#pragma unroll
            for (int i = 0; i < 4; ++i) {
                int cidx = tid + i * 256;
                int row = cidx >> 3, c16 = cidx & 7;
                uint32_t off = row * 128 + c16 * 16;
                uint32_t sw = off ^ ((off >> 3) & 0x70);
                size_t aoff = (size_t)(m0 + row) * DD + akoff + ks + (size_t)c16 * 8;
                size_t boff = (size_t)(n0 + row) * KK + bkoff + ks + (size_t)c16 * 8;
                cp16(abase + sw, g_xh + aoff);
                cp16(bbase + sw, g_wt + boff);
            }
        }
    };

    load_tile(0, 0); cp_commit();
    load_tile(1, 1); cp_commit();

    for (int kt = 0; kt < NKT_X; ++kt) {
        cp_wait<1>();
        __syncthreads();
        if (kt + 2 < NKT_X) load_tile(kt + 2, (kt + 2) % 3);
        cp_commit();
        uint32_t base = sb + (kt % 3) * STAGE_BYTES;
        mma_slab(acc, base + A_S0, base + B_S0, wc);
        mma_slab(acc, base + A_S1, base + B_S1, wc);
    }

#pragma unroll
    for (int i = 0; i < 2; ++i) {
        int row0 = m0 + (wid & 3) * 32 + i * 16 + (lane >> 2);
#pragma unroll
        for (int g = 0; g < 8; ++g) {
            int col = n0 + (wid >> 2) * 64 + g * 8 + (lane & 3) * 2;
            float2 bb = *(const float2*)&b[col];
            *(__half2*)&g_vxh[(size_t)row0 * GG + col] =
                __floats2half2_rn(acc[i][g][0] + bb.x, acc[i][g][1] + bb.y);
            *(__half2*)&g_vxh[(size_t)(row0 + 8) * GG + col] =
                __floats2half2_rn(acc[i][g][2] + bb.x, acc[i][g][3] + bb.y);
        }
    }
}

// ---------------- launch ---------------------------------------------------------
extern "C" void kernel_launch(void* const* d_in, const int* in_sizes, int n_in,
                              void* d_out, int out_size) {
    const float* x     = (const float*)d_in[0];   // (N, T, D)
    const float* A     = (const float*)d_in[1];   // (N, H, 4, 4)
    const float* Wx    = (const float*)d_in[2];   // (D, 4H)
    const float* Wh    = (const float*)d_in[3];   // (H, 4H)
    const float* Wattn = (const float*)d_in[4];   // (H, 4H)
    const float* b     = (const float*)d_in[5];   // (4H,)
    float* out = (float*)d_out;                   // (N, T, H)

    cudaFuncSetAttribute(gemm_step, cudaFuncAttributeMaxDynamicSharedMemorySize, GEMM_SMEM);
    cudaFuncSetAttribute(gemm_x,    cudaFuncAttributeMaxDynamicSharedMemorySize, GEMM_SMEM);

    prep_w<<<dim3(KK / 32, GG / 32), dim3(32, 8)>>>(Wx, Wh, Wattn);
    cvt_x<<<(NN * TT * DD) / 1024, 256>>>(x);
    cvt_A<<<(NN * HH * 16) / 1024, 256>>>(A);
    init_kernel<<<(NN * HH) / 256, 256>>>(A);
    gemm_x<<<dim3(GG / 128, (NN * TT) / 128), 256, GEMM_SMEM>>>(b);
    attn_kernel<<<NN, 256>>>();                      // attn from h0
    for (int t = 0; t < TT; ++t) {
        gemm_step<<<dim3(GG / 128, NN / 128), 256, GEMM_SMEM>>>();
        gate_attn<<<NN, 256>>>(out, t, (t + 1 < TT) ? 1 : 0);
    }
}

// round 11
// speedup vs baseline: 1.0308x; 1.0308x over previous
#include <cuda_runtime.h>
#include <cuda_fp16.h>
#include <cstdint>

#define NN 512
#define TT 32
#define DD 1024
#define HH 1024
#define GG 4096   // 4*H
#define KK 3072   // H + H + D

// ---------------- scratch (device globals; no allocation allowed) -------------
__device__ float g_c[NN * HH];
__device__ __align__(256) __half g_vh[(size_t)NN * GG];        // v (fp16)
__device__ __align__(256) __half g_vxh[(size_t)NN * TT * GG];  // precomputed x@Wx + b (fp16)
__device__ __align__(256) __half g_hh[NN * HH];       // h (fp16)
__device__ __align__(256) __half g_ah[NN * HH];       // attn (fp16)
__device__ __align__(256) __half g_xh[(size_t)NN * TT * DD];   // x (fp16)
__device__ __align__(256) __half g_Ah[(size_t)NN * HH * 16];   // A (fp16)
__device__ __align__(256) __half g_wt[(size_t)GG * KK];        // W^T fp16 [4096][3072]

// ---------------- small helpers ------------------------------------------------
__device__ __forceinline__ uint32_t smem_u32(const void* p) {
    uint32_t a;
    asm("{ .reg .u64 t; cvta.to.shared.u64 t, %1; cvt.u32.u64 %0, t; }" : "=r"(a) : "l"(p));
    return a;
}
__device__ __forceinline__ void cp16(uint32_t dst, const void* src) {
    asm volatile("cp.async.cg.shared.global [%0], [%1], 16;" :: "r"(dst), "l"(src));
}
__device__ __forceinline__ void cp_commit() { asm volatile("cp.async.commit_group;" ::: "memory"); }
template <int N> __device__ __forceinline__ void cp_wait() {
    asm volatile("cp.async.wait_group %0;" :: "n"(N) : "memory");
}
__device__ __forceinline__ void ldsm4(uint32_t& r0, uint32_t& r1, uint32_t& r2, uint32_t& r3,
                                      uint32_t addr) {
    asm volatile("ldmatrix.sync.aligned.m8n8.x4.shared.b16 {%0,%1,%2,%3}, [%4];"
                 : "=r"(r0), "=r"(r1), "=r"(r2), "=r"(r3) : "r"(addr));
}
__device__ __forceinline__ void mma16816(float* d, const uint32_t* a, uint32_t b0, uint32_t b1) {
    asm volatile(
        "mma.sync.aligned.m16n8k16.row.col.f32.f16.f16.f32 "
        "{%0,%1,%2,%3}, {%4,%5,%6,%7}, {%8,%9}, {%0,%1,%2,%3};"
        : "+f"(d[0]), "+f"(d[1]), "+f"(d[2]), "+f"(d[3])
        : "r"(a[0]), "r"(a[1]), "r"(a[2]), "r"(a[3]), "r"(b0), "r"(b1));
}

// ---------------- one-time prep kernels ----------------------------------------
__global__ void prep_w(const float* __restrict__ Wx, const float* __restrict__ Wh,
                       const float* __restrict__ Wattn) {
    __shared__ float tile[32][33];
    int k0 = blockIdx.x * 32, n0 = blockIdx.y * 32;
#pragma unroll
    for (int dy = 0; dy < 32; dy += 8) {
        int k = k0 + threadIdx.y + dy;
        int n = n0 + threadIdx.x;
        const float* W;
        int kk = k;
        if (k < 1024)       { W = Wh; }
        else if (k < 2048)  { W = Wattn; kk = k - 1024; }
        else                { W = Wx;    kk = k - 2048; }
        tile[threadIdx.y + dy][threadIdx.x] = W[(size_t)kk * GG + n];
    }
    __syncthreads();
#pragma unroll
    for (int dy = 0; dy < 32; dy += 8) {
        int n = n0 + threadIdx.y + dy;
        int k = k0 + threadIdx.x;
        g_wt[(size_t)n * KK + k] = __float2half(tile[threadIdx.x][threadIdx.y + dy]);
    }
}

__global__ void cvt_x(const float* __restrict__ src) {
    size_t i = (size_t)blockIdx.x * 256 + threadIdx.x;
    float4 f = ((const float4*)src)[i];
    union { uint2 u; __half2 h[2]; } U;
    U.h[0] = __floats2half2_rn(f.x, f.y);
    U.h[1] = __floats2half2_rn(f.z, f.w);
    ((uint2*)g_xh)[i] = U.u;
}
__global__ void cvt_A(const float* __restrict__ src) {
    size_t i = (size_t)blockIdx.x * 256 + threadIdx.x;
    float4 f = ((const float4*)src)[i];
    union { uint2 u; __half2 h[2]; } U;
    U.h[0] = __floats2half2_rn(f.x, f.y);
    U.h[1] = __floats2half2_rn(f.z, f.w);
    ((uint2*)g_Ah)[i] = U.u;
}

// ---------------- init: h0 = c0 = mean over the 16 spatial cells ---------------
__global__ void init_kernel(const float* __restrict__ A) {
    int idx = blockIdx.x * 256 + threadIdx.x;
    const float4* a4 = (const float4*)(A + (size_t)idx * 16);
    float4 a0 = a4[0], a1 = a4[1], a2 = a4[2], a3 = a4[3];
    float s = ((a0.x + a0.y) + (a0.z + a0.w)) + ((a1.x + a1.y) + (a1.z + a1.w))
            + ((a2.x + a2.y) + (a2.z + a2.w)) + ((a3.x + a3.y) + (a3.z + a3.w));
    s *= (1.0f / 16.0f);
    g_c[idx] = s;
    g_hh[idx] = __float2half(s);
}

// ---------------- attention over 16 spatial cells (A register-cached) ----------
__global__ __launch_bounds__(256) void attn_kernel() {
    int n = blockIdx.x;
    const __half* Af = g_Ah + (size_t)n * HH * 16;
    const __half* hp = g_hh + (size_t)n * HH;
    int tid = threadIdx.x;

    union Row { uint4 u[2]; __half2 h[8]; };
    Row ar[4];
    float hv[4];
#pragma unroll
    for (int r = 0; r < 4; ++r) {
        int j = tid + r * 256;
        ar[r].u[0] = *(const uint4*)(Af + (size_t)j * 16);
        ar[r].u[1] = *(const uint4*)(Af + (size_t)j * 16 + 8);
        hv[r] = __half2float(hp[j]);
    }

    float part[16];
#pragma unroll
    for (int k = 0; k < 16; ++k) part[k] = 0.0f;
#pragma unroll
    for (int r = 0; r < 4; ++r) {
#pragma unroll
        for (int q = 0; q < 8; ++q) {
            float2 f = __half22float2(ar[r].h[q]);
            part[2 * q]     += hv[r] * f.x;
            part[2 * q + 1] += hv[r] * f.y;
        }
    }
#pragma unroll
    for (int k = 0; k < 16; ++k)
#pragma unroll
        for (int off = 16; off; off >>= 1)
            part[k] += __shfl_xor_sync(0xffffffffu, part[k], off);

    __shared__ float sred[8][16];
    __shared__ float sM[16];
    int warp = tid >> 5, lane = tid & 31;
    if (lane == 0) {
#pragma unroll
        for (int k = 0; k < 16; ++k) sred[warp][k] = part[k];
    }
    __syncthreads();

    if (tid < 32) {
        int k = lane & 15;
        float s = 0.0f;
#pragma unroll
        for (int w = 0; w < 8; ++w) s += sred[w][k];
        s *= (1.0f / 32.0f);                         // / sqrt(H)
        float m = s;
#pragma unroll
        for (int off = 8; off; off >>= 1) m = fmaxf(m, __shfl_xor_sync(0xffffffffu, m, off));
        float e = expf(s - m);
        float sum = e;
#pragma unroll
        for (int off = 8; off; off >>= 1) sum += __shfl_xor_sync(0xffffffffu, sum, off);
        if (lane < 16) sM[lane] = e / sum;
    }
    __syncthreads();

#pragma unroll
    for (int r = 0; r < 4; ++r) {
        int j = tid + r * 256;
        float s = 0.0f;
#pragma unroll
        for (int q = 0; q < 8; ++q) {
            float2 f = __half22float2(ar[r].h[q]);
            s += f.x * sM[2 * q] + f.y * sM[2 * q + 1];
        }
        g_ah[(size_t)n * HH + j] = __float2half(s);
    }
}

// ---------------- shared GEMM machinery (fp16 1-pass, K=128 per stage) ----------
#define STAGE_BYTES 65536
#define A_S0 0
#define A_S1 16384
#define B_S0 32768
#define B_S1 49152
#define GEMM_SMEM (3 * STAGE_BYTES)

struct WarpCtx {
    uint32_t swb, aRow, aHalf, bRow, bHalf;
};
__device__ __forceinline__ WarpCtx warp_ctx(int wm, int wn, int lane) {
    WarpCtx c;
    c.swb   = (lane & 7) << 4;
    c.aRow  = (uint32_t)(wm * 32 + (lane & 15)) * 128;
    c.aHalf = (uint32_t)(lane >> 4);
    c.bRow  = (uint32_t)(wn * 64 + (lane & 7) + ((lane >> 4) << 3)) * 128;
    c.bHalf = (uint32_t)((lane >> 3) & 1);
    return c;
}

__device__ __forceinline__ void mma_slab(float acc[2][8][4], uint32_t a_base, uint32_t b_base,
                                         const WarpCtx& c) {
#pragma unroll
    for (int q = 0; q < 4; ++q) {
        uint32_t aChunk = ((2 * q + c.aHalf) << 4) ^ c.swb;
        uint32_t bChunk = ((2 * q + c.bHalf) << 4) ^ c.swb;
        uint32_t af[2][4];
#pragma unroll
        for (int i = 0; i < 2; ++i) {
            uint32_t ao = c.aRow + (uint32_t)i * 2048 + aChunk;
            ldsm4(af[i][0], af[i][1], af[i][2], af[i][3], a_base + ao);
        }
        uint32_t bf[4][4];
#pragma unroll
        for (int p = 0; p < 4; ++p) {
            uint32_t bo = c.bRow + (uint32_t)p * 2048 + bChunk;
            ldsm4(bf[p][0], bf[p][1], bf[p][2], bf[p][3], b_base + bo);
        }
#pragma unroll
        for (int i = 0; i < 2; ++i)
#pragma unroll
            for (int g = 0; g < 8; ++g) {
                mma16816(acc[i][g], af[i],
                         bf[g >> 1][(g & 1) * 2], bf[g >> 1][(g & 1) * 2 + 1]);
            }
    }
}

// ---------------- per-step GEMM: v = [h | attn] @ [Wh; Wattn]^T  (K=2048) -------
#define NKT_S 16   // 16 stages x K128
__global__ __launch_bounds__(256, 1) void gemm_step() {
    extern __shared__ char dynsmem[];
    uint32_t sb = smem_u32(dynsmem);
    const int tid = threadIdx.x;
    const int wid = tid >> 5, lane = tid & 31;
    const WarpCtx wc = warp_ctx(wid & 3, wid >> 2, lane);
    const int m0 = blockIdx.y * 128;
    const int n0 = blockIdx.x * 128;

    float acc[2][8][4];
#pragma unroll
    for (int i = 0; i < 2; ++i)
#pragma unroll
        for (int g = 0; g < 8; ++g)
#pragma unroll
            for (int r = 0; r < 4; ++r) acc[i][g][r] = 0.0f;

    auto load_tile = [&](int kt, int stage) {   // kt indexes K128 chunks
        uint32_t base = sb + stage * STAGE_BYTES;
        const __half* ap = (kt < 8) ? g_hh : g_ah;
        size_t akoff = (size_t)(kt & 7) * 128;
        size_t bkoff = (size_t)kt * 128;
#pragma unroll
        for (int slab = 0; slab < 2; ++slab) {
            uint32_t abase = base + (slab ? A_S1 : A_S0);
            uint32_t bbase = base + (slab ? B_S1 : B_S0);
            size_t ks = (size_t)slab * 64;
#pragma unroll
            for (int i = 0; i < 4; ++i) {
                int cidx = tid + i * 256;
                int row = cidx >> 3, c16 = cidx & 7;
                uint32_t off = row * 128 + c16 * 16;
                uint32_t sw = off ^ ((off >> 3) & 0x70);
                size_t aoff = (size_t)(m0 + row) * HH + akoff + ks + (size_t)c16 * 8;
                size_t boff = (size_t)(n0 + row) * KK + bkoff + ks + (size_t)c16 * 8;
                cp16(abase + sw, ap + aoff);
                cp16(bbase + sw, g_wt + boff);
            }
        }
    };

    load_tile(0, 0); cp_commit();
    load_tile(1, 1); cp_commit();

    for (int kt = 0; kt < NKT_S; ++kt) {
        cp_wait<1>();
        __syncthreads();                 // stage kt ready AND stage (kt+2)%3 free
        if (kt + 2 < NKT_S) load_tile(kt + 2, (kt + 2) % 3);
        cp_commit();
        uint32_t base = sb + (kt % 3) * STAGE_BYTES;
        mma_slab(acc, base + A_S0, base + B_S0, wc);
        mma_slab(acc, base + A_S1, base + B_S1, wc);
    }

#pragma unroll
    for (int i = 0; i < 2; ++i) {
        int row0 = m0 + (wid & 3) * 32 + i * 16 + (lane >> 2);
#pragma unroll
        for (int g = 0; g < 8; ++g) {
            int col = n0 + (wid >> 2) * 64 + g * 8 + (lane & 3) * 2;
            *(__half2*)&g_vh[(size_t)row0 * GG + col] =
                __floats2half2_rn(acc[i][g][0], acc[i][g][1]);
            *(__half2*)&g_vh[(size_t)(row0 + 8) * GG + col] =
                __floats2half2_rn(acc[i][g][2], acc[i][g][3]);
        }
    }
}

// ---------------- one-time GEMM: vx = X @ Wx^T + b  (M=16384, K=1024) -----------
#define NKT_X 8    // 8 stages x K128
__global__ __launch_bounds__(256, 1) void gemm_x(const float* __restrict__ b) {
    extern __shared__ char dynsmem[];
    uint32_t sb = smem_u32(dynsmem);
    const int tid = threadIdx.x;
    const int wid = tid >> 5, lane = tid & 31;
    const WarpCtx wc = warp_ctx(wid & 3, wid >> 2, lane);
    const int m0 = blockIdx.y * 128;
    const int n0 = blockIdx.x * 128;

    float acc[2][8][4];
#pragma unroll
    for (int i = 0; i < 2; ++i)
#pragma unroll
        for (int g = 0; g < 8; ++g)
#pragma unroll
            for (int r = 0; r < 4; ++r) acc[i][g][r] = 0.0f;

    auto load_tile = [&](int kt, int stage) {
        uint32_t base = sb + stage * STAGE_BYTES;
        size_t akoff = (size_t)kt * 128;
        size_t bkoff = 2048 + (size_t)kt * 128;
#pragma unroll
        for (int slab = 0; slab < 2; ++slab) {
            uint32_t abase = base + (slab ? A_S1 : A_S0);
            uint32_t bbase = base + (slab ? B_S1 : B_S0);
            size_t ks = (size_t)slab * 64;
#pragma unroll
            for (int i = 0; i < 4; ++i) {
                int cidx = tid + i * 256;
                int row = cidx >> 3, c16 = cidx & 7;
                uint32_t off = row * 128 + c16 * 16;
                uint32_t sw = off ^ ((off >> 3) & 0x70);
                size_t aoff = (size_t)(m0 + row) * DD + akoff + ks + (size_t)c16 * 8;
                size_t boff = (size_t)(n0 + row) * KK + bkoff + ks + (size_t)c16 * 8;
                cp16(abase + sw, g_xh + aoff);
                cp16(bbase + sw, g_wt + boff);
            }
        }
    };

    load_tile(0, 0); cp_commit();
    load_tile(1, 1); cp_commit();

    for (int kt = 0; kt < NKT_X; ++kt) {
        cp_wait<1>();
        __syncthreads();
        if (kt + 2 < NKT_X) load_tile(kt + 2, (kt + 2) % 3);
        cp_commit();
        uint32_t base = sb + (kt % 3) * STAGE_BYTES;
        mma_slab(acc, base + A_S0, base + B_S0, wc);
        mma_slab(acc, base + A_S1, base + B_S1, wc);
    }

#pragma unroll
    for (int i = 0; i < 2; ++i) {
        int row0 = m0 + (wid & 3) * 32 + i * 16 + (lane >> 2);
#pragma unroll
        for (int g = 0; g < 8; ++g) {
            int col = n0 + (wid >> 2) * 64 + g * 8 + (lane & 3) * 2;
            float2 bb = *(const float2*)&b[col];
            *(__half2*)&g_vxh[(size_t)row0 * GG + col] =
                __floats2half2_rn(acc[i][g][0] + bb.x, acc[i][g][1] + bb.y);
            *(__half2*)&g_vxh[(size_t)(row0 + 8) * GG + col] =
                __floats2half2_rn(acc[i][g][2] + bb.x, acc[i][g][3] + bb.y);
        }
    }
}

// ---------------- gates + state update + output write (2 j per thread) ---------
__global__ void gate_kernel(float* __restrict__ out, int t) {
    int idx2 = blockIdx.x * 256 + threadIdx.x;       // pair index
    int n = idx2 >> 9;
    int jj = (idx2 & 511) * 2;
    const __half* vr  = g_vh  + (size_t)n * GG;
    const __half* vxr = g_vxh + ((size_t)n * TT + t) * GG;

    float2 vi2 = __half22float2(*(const __half2*)&vr[jj]);
    float2 vf2 = __half22float2(*(const __half2*)&vr[jj + 1024]);
    float2 vo2 = __half22float2(*(const __half2*)&vr[jj + 2048]);
    float2 vg2 = __half22float2(*(const __half2*)&vr[jj + 3072]);
    float2 xi2 = __half22float2(*(const __half2*)&vxr[jj]);
    float2 xf2 = __half22float2(*(const __half2*)&vxr[jj + 1024]);
    float2 xo2 = __half22float2(*(const __half2*)&vxr[jj + 2048]);
    float2 xg2 = __half22float2(*(const __half2*)&vxr[jj + 3072]);

    size_t idx = (size_t)n * HH + jj;
    float2 c2 = *(const float2*)&g_c[idx];
    float h01[2], c01[2];
#pragma unroll
    for (int u = 0; u < 2; ++u) {
        float vi = (u ? vi2.y + xi2.y : vi2.x + xi2.x);
        float vf = (u ? vf2.y + xf2.y : vf2.x + xf2.x);
        float vo = (u ? vo2.y + xo2.y : vo2.x + xo2.x);
        float vg = (u ? vg2.y + xg2.y : vg2.x + xg2.x);
        float ig = 1.0f / (1.0f + expf(-vi));
        float fg = 1.0f / (1.0f + expf(-vf));
        float og = 1.0f / (1.0f + expf(-vo));
        float gg = tanhf(vg);
        float c = fg * (u ? c2.y : c2.x) + ig * gg;
        c01[u] = c;
        h01[u] = og * tanhf(c);
    }
    *(float2*)&g_c[idx] = make_float2(c01[0], c01[1]);
    *(__half2*)&g_hh[idx] = __floats2half2_rn(h01[0], h01[1]);
    *(float2*)&out[(size_t)n * (TT * HH) + (size_t)t * HH + jj] = make_float2(h01[0], h01[1]);
}

// ---------------- launch ---------------------------------------------------------
extern "C" void kernel_launch(void* const* d_in, const int* in_sizes, int n_in,
                              void* d_out, int out_size) {
    const float* x     = (const float*)d_in[0];   // (N, T, D)
    const float* A     = (const float*)d_in[1];   // (N, H, 4, 4)
    const float* Wx    = (const float*)d_in[2];   // (D, 4H)
    const float* Wh    = (const float*)d_in[3];   // (H, 4H)
    const float* Wattn = (const float*)d_in[4];   // (H, 4H)
    const float* b     = (const float*)d_in[5];   // (4H,)
    float* out = (float*)d_out;                   // (N, T, H)

    cudaFuncSetAttribute(gemm_step, cudaFuncAttributeMaxDynamicSharedMemorySize, GEMM_SMEM);
    cudaFuncSetAttribute(gemm_x,    cudaFuncAttributeMaxDynamicSharedMemorySize, GEMM_SMEM);

    prep_w<<<dim3(KK / 32, GG / 32), dim3(32, 8)>>>(Wx, Wh, Wattn);
    cvt_x<<<(NN * TT * DD) / 1024, 256>>>(x);
    cvt_A<<<(NN * HH * 16) / 1024, 256>>>(A);
    init_kernel<<<(NN * HH) / 256, 256>>>(A);
    gemm_x<<<dim3(GG / 128, (NN * TT) / 128), 256, GEMM_SMEM>>>(b);
    for (int t = 0; t < TT; ++t) {
        attn_kernel<<<NN, 256>>>();
        gemm_step<<<dim3(GG / 128, NN / 128), 256, GEMM_SMEM>>>();
        gate_kernel<<<(NN * HH) / 512, 256>>>(out, t);
    }
}

// round 14
// speedup vs baseline: 1.0577x; 1.0261x over previous
#include <cuda_runtime.h>
#include <cuda_fp16.h>
#include <cstdint>

#define NN 512
#define TT 32
#define DD 1024
#define HH 1024
#define GG 4096   // 4*H
#define KK 3072   // H + H + D

// ---------------- scratch (device globals; no allocation allowed) -------------
__device__ float g_c[NN * HH];
__device__ __align__(256) __half g_vh[(size_t)NN * GG];        // v (fp16)
__device__ __align__(256) __half g_vxh[(size_t)NN * TT * GG];  // x@Wx + b, layout [t][n][4H]
__device__ __align__(256) __half g_hh[NN * HH];       // h (fp16)
__device__ __align__(256) __half g_ah[NN * HH];       // attn (fp16)
__device__ __align__(256) __half g_xh[(size_t)NN * TT * DD];   // x (fp16)
__device__ __align__(256) __half g_Ah[(size_t)NN * HH * 16];   // A (fp16)
__device__ __align__(256) __half g_wt[(size_t)GG * KK];        // W^T fp16 [4096][3072]

// ---------------- small helpers ------------------------------------------------
__device__ __forceinline__ uint32_t smem_u32(const void* p) {
    uint32_t a;
    asm("{ .reg .u64 t; cvta.to.shared.u64 t, %1; cvt.u32.u64 %0, t; }" : "=r"(a) : "l"(p));
    return a;
}
__device__ __forceinline__ void cp16(uint32_t dst, const void* src) {
    asm volatile("cp.async.cg.shared.global [%0], [%1], 16;" :: "r"(dst), "l"(src));
}
__device__ __forceinline__ void cp_commit() { asm volatile("cp.async.commit_group;" ::: "memory"); }
template <int N> __device__ __forceinline__ void cp_wait() {
    asm volatile("cp.async.wait_group %0;" :: "n"(N) : "memory");
}
__device__ __forceinline__ void ldsm4(uint32_t& r0, uint32_t& r1, uint32_t& r2, uint32_t& r3,
                                      uint32_t addr) {
    asm volatile("ldmatrix.sync.aligned.m8n8.x4.shared.b16 {%0,%1,%2,%3}, [%4];"
                 : "=r"(r0), "=r"(r1), "=r"(r2), "=r"(r3) : "r"(addr));
}
__device__ __forceinline__ void mma16816(float* d, const uint32_t* a, uint32_t b0, uint32_t b1) {
    asm volatile(
        "mma.sync.aligned.m16n8k16.row.col.f32.f16.f16.f32 "
        "{%0,%1,%2,%3}, {%4,%5,%6,%7}, {%8,%9}, {%0,%1,%2,%3};"
        : "+f"(d[0]), "+f"(d[1]), "+f"(d[2]), "+f"(d[3])
        : "r"(a[0]), "r"(a[1]), "r"(a[2]), "r"(a[3]), "r"(b0), "r"(b1));
}

// ---------------- one-time prep kernels ----------------------------------------
__global__ void prep_w(const float* __restrict__ Wx, const float* __restrict__ Wh,
                       const float* __restrict__ Wattn) {
    __shared__ float tile[32][33];
    int k0 = blockIdx.x * 32, n0 = blockIdx.y * 32;
#pragma unroll
    for (int dy = 0; dy < 32; dy += 8) {
        int k = k0 + threadIdx.y + dy;
        int n = n0 + threadIdx.x;
        const float* W;
        int kk = k;
        if (k < 1024)       { W = Wh; }
        else if (k < 2048)  { W = Wattn; kk = k - 1024; }
        else                { W = Wx;    kk = k - 2048; }
        tile[threadIdx.y + dy][threadIdx.x] = W[(size_t)kk * GG + n];
    }
    __syncthreads();
#pragma unroll
    for (int dy = 0; dy < 32; dy += 8) {
        int n = n0 + threadIdx.y + dy;
        int k = k0 + threadIdx.x;
        g_wt[(size_t)n * KK + k] = __float2half(tile[threadIdx.x][threadIdx.y + dy]);
    }
}

__global__ void cvt_x(const float* __restrict__ src) {
    size_t i = (size_t)blockIdx.x * 256 + threadIdx.x;
    float4 f = ((const float4*)src)[i];
    union { uint2 u; __half2 h[2]; } U;
    U.h[0] = __floats2half2_rn(f.x, f.y);
    U.h[1] = __floats2half2_rn(f.z, f.w);
    ((uint2*)g_xh)[i] = U.u;
}
__global__ void cvt_A(const float* __restrict__ src) {
    size_t i = (size_t)blockIdx.x * 256 + threadIdx.x;
    float4 f = ((const float4*)src)[i];
    union { uint2 u; __half2 h[2]; } U;
    U.h[0] = __floats2half2_rn(f.x, f.y);
    U.h[1] = __floats2half2_rn(f.z, f.w);
    ((uint2*)g_Ah)[i] = U.u;
}

// ---------------- init: h0 = c0 = mean over the 16 spatial cells ---------------
__global__ void init_kernel(const float* __restrict__ A) {
    int idx = blockIdx.x * 256 + threadIdx.x;
    const float4* a4 = (const float4*)(A + (size_t)idx * 16);
    float4 a0 = a4[0], a1 = a4[1], a2 = a4[2], a3 = a4[3];
    float s = ((a0.x + a0.y) + (a0.z + a0.w)) + ((a1.x + a1.y) + (a1.z + a1.w))
            + ((a2.x + a2.y) + (a2.z + a2.w)) + ((a3.x + a3.y) + (a3.z + a3.w));
    s *= (1.0f / 16.0f);
    g_c[idx] = s;
    g_hh[idx] = __float2half(s);
}

// ---------------- attention over 16 spatial cells (A register-cached) ----------
__global__ __launch_bounds__(256) void attn_kernel() {
    int n = blockIdx.x;
    const __half* Af = g_Ah + (size_t)n * HH * 16;
    const __half* hp = g_hh + (size_t)n * HH;
    int tid = threadIdx.x;

    union Row { uint4 u[2]; __half2 h[8]; };
    Row ar[4];
    float hv[4];
#pragma unroll
    for (int r = 0; r < 4; ++r) {
        int j = tid + r * 256;
        ar[r].u[0] = *(const uint4*)(Af + (size_t)j * 16);
        ar[r].u[1] = *(const uint4*)(Af + (size_t)j * 16 + 8);
        hv[r] = __half2float(hp[j]);
    }

    float part[16];
#pragma unroll
    for (int k = 0; k < 16; ++k) part[k] = 0.0f;
#pragma unroll
    for (int r = 0; r < 4; ++r) {
#pragma unroll
        for (int q = 0; q < 8; ++q) {
            float2 f = __half22float2(ar[r].h[q]);
            part[2 * q]     += hv[r] * f.x;
            part[2 * q + 1] += hv[r] * f.y;
        }
    }
#pragma unroll
    for (int k = 0; k < 16; ++k)
#pragma unroll
        for (int off = 16; off; off >>= 1)
            part[k] += __shfl_xor_sync(0xffffffffu, part[k], off);

    __shared__ float sred[8][16];
    __shared__ float sM[16];
    int warp = tid >> 5, lane = tid & 31;
    if (lane == 0) {
#pragma unroll
        for (int k = 0; k < 16; ++k) sred[warp][k] = part[k];
    }
    __syncthreads();

    if (tid < 32) {
        int k = lane & 15;
        float s = 0.0f;
#pragma unroll
        for (int w = 0; w < 8; ++w) s += sred[w][k];
        s *= (1.0f / 32.0f);                         // / sqrt(H)
        float m = s;
#pragma unroll
        for (int off = 8; off; off >>= 1) m = fmaxf(m, __shfl_xor_sync(0xffffffffu, m, off));
        float e = expf(s - m);
        float sum = e;
#pragma unroll
        for (int off = 8; off; off >>= 1) sum += __shfl_xor_sync(0xffffffffu, sum, off);
        if (lane < 16) sM[lane] = e / sum;
    }
    __syncthreads();

#pragma unroll
    for (int r = 0; r < 4; ++r) {
        int j = tid + r * 256;
        float s = 0.0f;
#pragma unroll
        for (int q = 0; q < 8; ++q) {
            float2 f = __half22float2(ar[r].h[q]);
            s += f.x * sM[2 * q] + f.y * sM[2 * q + 1];
        }
        g_ah[(size_t)n * HH + j] = __float2half(s);
    }
}

// ---------------- shared GEMM machinery (fp16 1-pass, K=128 per stage) ----------
#define STAGE_BYTES 65536
#define A_S0 0
#define A_S1 16384
#define B_S0 32768
#define B_S1 49152
#define GEMM_SMEM (3 * STAGE_BYTES)

struct WarpCtx {
    uint32_t swb, aRow, aHalf, bRow, bHalf;
};
__device__ __forceinline__ WarpCtx warp_ctx(int wm, int wn, int lane) {
    WarpCtx c;
    c.swb   = (lane & 7) << 4;
    c.aRow  = (uint32_t)(wm * 32 + (lane & 15)) * 128;
    c.aHalf = (uint32_t)(lane >> 4);
    c.bRow  = (uint32_t)(wn * 64 + (lane & 7) + ((lane >> 4) << 3)) * 128;
    c.bHalf = (uint32_t)((lane >> 3) & 1);
    return c;
}

__device__ __forceinline__ void mma_slab(float acc[2][8][4], uint32_t a_base, uint32_t b_base,
                                         const WarpCtx& c) {
#pragma unroll
    for (int q = 0; q < 4; ++q) {
        uint32_t aChunk = ((2 * q + c.aHalf) << 4) ^ c.swb;
        uint32_t bChunk = ((2 * q + c.bHalf) << 4) ^ c.swb;
        uint32_t af[2][4];
#pragma unroll
        for (int i = 0; i < 2; ++i) {
            uint32_t ao = c.aRow + (uint32_t)i * 2048 + aChunk;
            ldsm4(af[i][0], af[i][1], af[i][2], af[i][3], a_base + ao);
        }
        uint32_t bf[4][4];
#pragma unroll
        for (int p = 0; p < 4; ++p) {
            uint32_t bo = c.bRow + (uint32_t)p * 2048 + bChunk;
            ldsm4(bf[p][0], bf[p][1], bf[p][2], bf[p][3], b_base + bo);
        }
#pragma unroll
        for (int i = 0; i < 2; ++i)
#pragma unroll
            for (int g = 0; g < 8; ++g) {
                mma16816(acc[i][g], af[i],
                         bf[g >> 1][(g & 1) * 2], bf[g >> 1][(g & 1) * 2 + 1]);
            }
    }
}

// ---------------- per-step GEMM: v = [h | attn] @ [Wh; Wattn]^T  (K=2048) -------
#define NKT_S 16   // 16 stages x K128
__global__ __launch_bounds__(256, 1) void gemm_step() {
    extern __shared__ char dynsmem[];
    uint32_t sb = smem_u32(dynsmem);
    const int tid = threadIdx.x;
    const int wid = tid >> 5, lane = tid & 31;
    const WarpCtx wc = warp_ctx(wid & 3, wid >> 2, lane);
    const int m0 = blockIdx.y * 128;
    const int n0 = blockIdx.x * 128;

    float acc[2][8][4];
#pragma unroll
    for (int i = 0; i < 2; ++i)
#pragma unroll
        for (int g = 0; g < 8; ++g)
#pragma unroll
            for (int r = 0; r < 4; ++r) acc[i][g][r] = 0.0f;

    auto load_tile = [&](int kt, int stage) {   // kt indexes K128 chunks
        uint32_t base = sb + stage * STAGE_BYTES;
        const __half* ap = (kt < 8) ? g_hh : g_ah;
        size_t akoff = (size_t)(kt & 7) * 128;
        size_t bkoff = (size_t)kt * 128;
#pragma unroll
        for (int slab = 0; slab < 2; ++slab) {
            uint32_t abase = base + (slab ? A_S1 : A_S0);
            uint32_t bbase = base + (slab ? B_S1 : B_S0);
            size_t ks = (size_t)slab * 64;
#pragma unroll
            for (int i = 0; i < 4; ++i) {
                int cidx = tid + i * 256;
                int row = cidx >> 3, c16 = cidx & 7;
                uint32_t off = row * 128 + c16 * 16;
                uint32_t sw = off ^ ((off >> 3) & 0x70);
                size_t aoff = (size_t)(m0 + row) * HH + akoff + ks + (size_t)c16 * 8;
                size_t boff = (size_t)(n0 + row) * KK + bkoff + ks + (size_t)c16 * 8;
                cp16(abase + sw, ap + aoff);
                cp16(bbase + sw, g_wt + boff);
            }
        }
    };

    load_tile(0, 0); cp_commit();
    load_tile(1, 1); cp_commit();

    for (int kt = 0; kt < NKT_S; ++kt) {
        cp_wait<1>();
        __syncthreads();                 // stage kt ready AND stage (kt+2)%3 free
        if (kt + 2 < NKT_S) load_tile(kt + 2, (kt + 2) % 3);
        cp_commit();
        uint32_t base = sb + (kt % 3) * STAGE_BYTES;
        mma_slab(acc, base + A_S0, base + B_S0, wc);
        mma_slab(acc, base + A_S1, base + B_S1, wc);
    }

#pragma unroll
    for (int i = 0; i < 2; ++i) {
        int row0 = m0 + (wid & 3) * 32 + i * 16 + (lane >> 2);
#pragma unroll
        for (int g = 0; g < 8; ++g) {
            int col = n0 + (wid >> 2) * 64 + g * 8 + (lane & 3) * 2;
            *(__half2*)&g_vh[(size_t)row0 * GG + col] =
                __floats2half2_rn(acc[i][g][0], acc[i][g][1]);
            *(__half2*)&g_vh[(size_t)(row0 + 8) * GG + col] =
                __floats2half2_rn(acc[i][g][2], acc[i][g][3]);
        }
    }
}

// ---------------- chunked GEMM: vx[t][n] = x[n,t] @ Wx^T + b  --------------------
// One chunk = 4 timesteps: M = 2048 rows, m = t*512 + n (t = ci*4 + by/4, n0 = (by&3)*128)
#define NKT_X 8    // 8 stages x K128
__global__ __launch_bounds__(256, 1) void gemm_x_chunk(const float* __restrict__ b, int ci) {
    extern __shared__ char dynsmem[];
    uint32_t sb = smem_u32(dynsmem);
    const int tid = threadIdx.x;
    const int wid = tid >> 5, lane = tid & 31;
    const WarpCtx wc = warp_ctx(wid & 3, wid >> 2, lane);
    const int m0 = ci * 2048 + blockIdx.y * 128;       // global m = t*512 + n
    const int tt = m0 >> 9;                            // timestep of this block
    const int nb = m0 & 511;                           // n offset of row 0
    const int n0 = blockIdx.x * 128;

    float acc[2][8][4];
#pragma unroll
    for (int i = 0; i < 2; ++i)
#pragma unroll
        for (int g = 0; g < 8; ++g)
#pragma unroll
            for (int r = 0; r < 4; ++r) acc[i][g][r] = 0.0f;

    auto load_tile = [&](int kt, int stage) {
        uint32_t base = sb + stage * STAGE_BYTES;
        size_t akoff = (size_t)kt * 128;
        size_t bkoff = 2048 + (size_t)kt * 128;
#pragma unroll
        for (int slab = 0; slab < 2; ++slab) {
            uint32_t abase = base + (slab ? A_S1 : A_S0);
            uint32_t bbase = base + (slab ? B_S1 : B_S0);
            size_t ks = (size_t)slab * 64;
#pragma unroll
            for (int i = 0; i < 4; ++i) {
                int cidx = tid + i * 256;
                int row = cidx >> 3, c16 = cidx & 7;
                uint32_t off = row * 128 + c16 * 16;
                uint32_t sw = off ^ ((off >> 3) & 0x70);
                size_t aoff = ((size_t)(nb + row) * TT + tt) * DD + akoff + ks + (size_t)c16 * 8;
                size_t boff = (size_t)(n0 + row) * KK + bkoff + ks + (size_t)c16 * 8;
                cp16(abase + sw, g_xh + aoff);
                cp16(bbase + sw, g_wt + boff);
            }
        }
    };

    load_tile(0, 0); cp_commit();
    load_tile(1, 1); cp_commit();

    for (int kt = 0; kt < NKT_X; ++kt) {
        cp_wait<1>();
        __syncthreads();
        if (kt + 2 < NKT_X) load_tile(kt + 2, (kt + 2) % 3);
        cp_commit();
        uint32_t base = sb + (kt % 3) * STAGE_BYTES;
        mma_slab(acc, base + A_S0, base + B_S0, wc);
        mma_slab(acc, base + A_S1, base + B_S1, wc);
    }

#pragma unroll
    for (int i = 0; i < 2; ++i) {
        int row0 = m0 + (wid & 3) * 32 + i * 16 + (lane >> 2);
#pragma unroll
        for (int g = 0; g < 8; ++g) {
            int col = n0 + (wid >> 2) * 64 + g * 8 + (lane & 3) * 2;
            float2 bb = *(const float2*)&b[col];
            *(__half2*)&g_vxh[(size_t)row0 * GG + col] =
                __floats2half2_rn(acc[i][g][0] + bb.x, acc[i][g][1] + bb.y);
            *(__half2*)&g_vxh[(size_t)(row0 + 8) * GG + col] =
                __floats2half2_rn(acc[i][g][2] + bb.x, acc[i][g][3] + bb.y);
        }
    }
}

// ---------------- gates + state update + output write (2 j per thread) ---------
__global__ void gate_kernel(float* __restrict__ out, int t) {
    int idx2 = blockIdx.x * 256 + threadIdx.x;       // pair index
    int n = idx2 >> 9;
    int jj = (idx2 & 511) * 2;
    const __half* vr  = g_vh  + (size_t)n * GG;
    const __half* vxr = g_vxh + ((size_t)t * NN + n) * GG;   // [t][n][4H]

    float2 vi2 = __half22float2(*(const __half2*)&vr[jj]);
    float2 vf2 = __half22float2(*(const __half2*)&vr[jj + 1024]);
    float2 vo2 = __half22float2(*(const __half2*)&vr[jj + 2048]);
    float2 vg2 = __half22float2(*(const __half2*)&vr[jj + 3072]);
    float2 xi2 = __half22float2(*(const __half2*)&vxr[jj]);
    float2 xf2 = __half22float2(*(const __half2*)&vxr[jj + 1024]);
    float2 xo2 = __half22float2(*(const __half2*)&vxr[jj + 2048]);
    float2 xg2 = __half22float2(*(const __half2*)&vxr[jj + 3072]);

    size_t idx = (size_t)n * HH + jj;
    float2 c2 = *(const float2*)&g_c[idx];
    float h01[2], c01[2];
#pragma unroll
    for (int u = 0; u < 2; ++u) {
        float vi = (u ? vi2.y + xi2.y : vi2.x + xi2.x);
        float vf = (u ? vf2.y + xf2.y : vf2.x + xf2.x);
        float vo = (u ? vo2.y + xo2.y : vo2.x + xo2.x);
        float vg = (u ? vg2.y + xg2.y : vg2.x + xg2.x);
        float ig = 1.0f / (1.0f + expf(-vi));
        float fg = 1.0f / (1.0f + expf(-vf));
        float og = 1.0f / (1.0f + expf(-vo));
        float gg = tanhf(vg);
        float c = fg * (u ? c2.y : c2.x) + ig * gg;
        c01[u] = c;
        h01[u] = og * tanhf(c);
    }
    *(float2*)&g_c[idx] = make_float2(c01[0], c01[1]);
    *(__half2*)&g_hh[idx] = __floats2half2_rn(h01[0], h01[1]);
    *(float2*)&out[(size_t)n * (TT * HH) + (size_t)t * HH + jj] = make_float2(h01[0], h01[1]);
}

// ---------------- launch ---------------------------------------------------------
extern "C" void kernel_launch(void* const* d_in, const int* in_sizes, int n_in,
                              void* d_out, int out_size) {
    const float* x     = (const float*)d_in[0];   // (N, T, D)
    const float* A     = (const float*)d_in[1];   // (N, H, 4, 4)
    const float* Wx    = (const float*)d_in[2];   // (D, 4H)
    const float* Wh    = (const float*)d_in[3];   // (H, 4H)
    const float* Wattn = (const float*)d_in[4];   // (H, 4H)
    const float* b     = (const float*)d_in[5];   // (4H,)
    float* out = (float*)d_out;                   // (N, T, H)

    cudaFuncSetAttribute(gemm_step,    cudaFuncAttributeMaxDynamicSharedMemorySize, GEMM_SMEM);
    cudaFuncSetAttribute(gemm_x_chunk, cudaFuncAttributeMaxDynamicSharedMemorySize, GEMM_SMEM);

    // kernel_launch runs exactly twice (correctness + capture); create fresh
    // stream/events per call — host-side only, no device allocation.
    cudaStream_t s2;
    cudaStreamCreateWithFlags(&s2, cudaStreamNonBlocking);
    cudaEvent_t evFork;
    cudaEventCreateWithFlags(&evFork, cudaEventDisableTiming);
    cudaEvent_t evChunk[8];
    for (int i = 0; i < 8; ++i) cudaEventCreateWithFlags(&evChunk[i], cudaEventDisableTiming);

    prep_w<<<dim3(KK / 32, GG / 32), dim3(32, 8)>>>(Wx, Wh, Wattn);
    cvt_x<<<(NN * TT * DD) / 1024, 256>>>(x);
    cvt_A<<<(NN * HH * 16) / 1024, 256>>>(A);
    init_kernel<<<(NN * HH) / 256, 256>>>(A);

    // fork: gemm_x chunks on s2, overlapping with the recurrent loop
    cudaEventRecord(evFork, 0);
    cudaStreamWaitEvent(s2, evFork, 0);
    for (int ci = 0; ci < 8; ++ci) {
        gemm_x_chunk<<<dim3(GG / 128, 16), 256, GEMM_SMEM, s2>>>(b, ci);
        cudaEventRecord(evChunk[ci], s2);
    }

    for (int t = 0; t < TT; ++t) {
        attn_kernel<<<NN, 256>>>();
        gemm_step<<<dim3(GG / 128, NN / 128), 256, GEMM_SMEM>>>();
        if ((t & 3) == 0) cudaStreamWaitEvent(0, evChunk[t >> 2], 0);   // join chunk t/4
        gate_kernel<<<(NN * HH) / 512, 256>>>(out, t);
    }

    // events/stream are leaked intentionally (2 calls total); destroying a
    // capturing-referenced stream mid-capture is the riskier path.
    for (int i = 0; i < 8; ++i) cudaEventDestroy(evChunk[i]);
    cudaEventDestroy(evFork);
    cudaStreamDestroy(s2);
}

// round 15
// speedup vs baseline: 1.0577x; 1.0000x over previous
#include <cuda_runtime.h>
#include <cuda_fp16.h>
#include <cstdint>

#define NN 512
#define TT 32
#define DD 1024
#define HH 1024
#define GG 4096   // 4*H
#define KK 3072   // H + H + D

// ---------------- scratch (device globals; no allocation allowed) -------------
__device__ float g_c[NN * HH];
__device__ __align__(256) __half g_vh[(size_t)NN * GG];        // v (fp16)
__device__ __align__(256) __half g_vxh[(size_t)NN * TT * GG];  // x@Wx + b, layout [t][n][4H]
__device__ __align__(256) __half g_hh[NN * HH];       // h (fp16)
__device__ __align__(256) __half g_ah[NN * HH];       // attn (fp16)
__device__ __align__(256) __half g_xh[(size_t)NN * TT * DD];   // x (fp16)
__device__ __align__(256) __half g_Ah[(size_t)NN * HH * 16];   // A (fp16)
__device__ __align__(256) __half g_wt[(size_t)GG * KK];        // W^T fp16 [4096][3072]

// ---------------- small helpers ------------------------------------------------
__device__ __forceinline__ uint32_t smem_u32(const void* p) {
    uint32_t a;
    asm("{ .reg .u64 t; cvta.to.shared.u64 t, %1; cvt.u32.u64 %0, t; }" : "=r"(a) : "l"(p));
    return a;
}
__device__ __forceinline__ void cp16(uint32_t dst, const void* src) {
    asm volatile("cp.async.cg.shared.global [%0], [%1], 16;" :: "r"(dst), "l"(src));
}
__device__ __forceinline__ void cp_commit() { asm volatile("cp.async.commit_group;" ::: "memory"); }
template <int N> __device__ __forceinline__ void cp_wait() {
    asm volatile("cp.async.wait_group %0;" :: "n"(N) : "memory");
}
__device__ __forceinline__ void ldsm4(uint32_t& r0, uint32_t& r1, uint32_t& r2, uint32_t& r3,
                                      uint32_t addr) {
    asm volatile("ldmatrix.sync.aligned.m8n8.x4.shared.b16 {%0,%1,%2,%3}, [%4];"
                 : "=r"(r0), "=r"(r1), "=r"(r2), "=r"(r3) : "r"(addr));
}
__device__ __forceinline__ void mma16816(float* d, const uint32_t* a, uint32_t b0, uint32_t b1) {
    asm volatile(
        "mma.sync.aligned.m16n8k16.row.col.f32.f16.f16.f32 "
        "{%0,%1,%2,%3}, {%4,%5,%6,%7}, {%8,%9}, {%0,%1,%2,%3};"
        : "+f"(d[0]), "+f"(d[1]), "+f"(d[2]), "+f"(d[3])
        : "r"(a[0]), "r"(a[1]), "r"(a[2]), "r"(a[3]), "r"(b0), "r"(b1));
}

// ---------------- one-time prep kernels ----------------------------------------
__global__ void prep_w(const float* __restrict__ Wx, const float* __restrict__ Wh,
                       const float* __restrict__ Wattn) {
    __shared__ float tile[32][33];
    int k0 = blockIdx.x * 32, n0 = blockIdx.y * 32;
#pragma unroll
    for (int dy = 0; dy < 32; dy += 8) {
        int k = k0 + threadIdx.y + dy;
        int n = n0 + threadIdx.x;
        const float* W;
        int kk = k;
        if (k < 1024)       { W = Wh; }
        else if (k < 2048)  { W = Wattn; kk = k - 1024; }
        else                { W = Wx;    kk = k - 2048; }
        tile[threadIdx.y + dy][threadIdx.x] = W[(size_t)kk * GG + n];
    }
    __syncthreads();
#pragma unroll
    for (int dy = 0; dy < 32; dy += 8) {
        int n = n0 + threadIdx.y + dy;
        int k = k0 + threadIdx.x;
        g_wt[(size_t)n * KK + k] = __float2half(tile[threadIdx.x][threadIdx.y + dy]);
    }
}

__global__ void cvt_x(const float* __restrict__ src) {
    size_t i = (size_t)blockIdx.x * 256 + threadIdx.x;
    float4 f = ((const float4*)src)[i];
    union { uint2 u; __half2 h[2]; } U;
    U.h[0] = __floats2half2_rn(f.x, f.y);
    U.h[1] = __floats2half2_rn(f.z, f.w);
    ((uint2*)g_xh)[i] = U.u;
}
__global__ void cvt_A(const float* __restrict__ src) {
    size_t i = (size_t)blockIdx.x * 256 + threadIdx.x;
    float4 f = ((const float4*)src)[i];
    union { uint2 u; __half2 h[2]; } U;
    U.h[0] = __floats2half2_rn(f.x, f.y);
    U.h[1] = __floats2half2_rn(f.z, f.w);
    ((uint2*)g_Ah)[i] = U.u;
}

// ---------------- init: h0 = c0 = mean over the 16 spatial cells ---------------
__global__ void init_kernel(const float* __restrict__ A) {
    int idx = blockIdx.x * 256 + threadIdx.x;
    const float4* a4 = (const float4*)(A + (size_t)idx * 16);
    float4 a0 = a4[0], a1 = a4[1], a2 = a4[2], a3 = a4[3];
    float s = ((a0.x + a0.y) + (a0.z + a0.w)) + ((a1.x + a1.y) + (a1.z + a1.w))
            + ((a2.x + a2.y) + (a2.z + a2.w)) + ((a3.x + a3.y) + (a3.z + a3.w));
    s *= (1.0f / 16.0f);
    g_c[idx] = s;
    g_hh[idx] = __float2half(s);
}

// ---------------- attention over 16 spatial cells (A register-cached) ----------
__global__ __launch_bounds__(256) void attn_kernel() {
    int n = blockIdx.x;
    const __half* Af = g_Ah + (size_t)n * HH * 16;
    const __half* hp = g_hh + (size_t)n * HH;
    int tid = threadIdx.x;

    union Row { uint4 u[2]; __half2 h[8]; };
    Row ar[4];
    float hv[4];
#pragma unroll
    for (int r = 0; r < 4; ++r) {
        int j = tid + r * 256;
        ar[r].u[0] = *(const uint4*)(Af + (size_t)j * 16);
        ar[r].u[1] = *(const uint4*)(Af + (size_t)j * 16 + 8);
        hv[r] = __half2float(hp[j]);
    }

    float part[16];
#pragma unroll
    for (int k = 0; k < 16; ++k) part[k] = 0.0f;
#pragma unroll
    for (int r = 0; r < 4; ++r) {
#pragma unroll
        for (int q = 0; q < 8; ++q) {
            float2 f = __half22float2(ar[r].h[q]);
            part[2 * q]     += hv[r] * f.x;
            part[2 * q + 1] += hv[r] * f.y;
        }
    }
#pragma unroll
    for (int k = 0; k < 16; ++k)
#pragma unroll
        for (int off = 16; off; off >>= 1)
            part[k] += __shfl_xor_sync(0xffffffffu, part[k], off);

    __shared__ float sred[8][16];
    __shared__ float sM[16];
    int warp = tid >> 5, lane = tid & 31;
    if (lane == 0) {
#pragma unroll
        for (int k = 0; k < 16; ++k) sred[warp][k] = part[k];
    }
    __syncthreads();

    if (tid < 32) {
        int k = lane & 15;
        float s = 0.0f;
#pragma unroll
        for (int w = 0; w < 8; ++w) s += sred[w][k];
        s *= (1.0f / 32.0f);                         // / sqrt(H)
        float m = s;
#pragma unroll
        for (int off = 8; off; off >>= 1) m = fmaxf(m, __shfl_xor_sync(0xffffffffu, m, off));
        float e = expf(s - m);
        float sum = e;
#pragma unroll
        for (int off = 8; off; off >>= 1) sum += __shfl_xor_sync(0xffffffffu, sum, off);
        if (lane < 16) sM[lane] = e / sum;
    }
    __syncthreads();

#pragma unroll
    for (int r = 0; r < 4; ++r) {
        int j = tid + r * 256;
        float s = 0.0f;
#pragma unroll
        for (int q = 0; q < 8; ++q) {
            float2 f = __half22float2(ar[r].h[q]);
            s += f.x * sM[2 * q] + f.y * sM[2 * q + 1];
        }
        g_ah[(size_t)n * HH + j] = __float2half(s);
    }
}

// ---------------- shared GEMM machinery (fp16 1-pass, K=128 per stage) ----------
#define STAGE_BYTES 65536
#define A_S0 0
#define A_S1 16384
#define B_S0 32768
#define B_S1 49152
#define GEMM_SMEM (3 * STAGE_BYTES)

struct WarpCtx {
    uint32_t swb, aRow, aHalf, bRow, bHalf;
};
__device__ __forceinline__ WarpCtx warp_ctx(int wm, int wn, int lane) {
    WarpCtx c;
    c.swb   = (lane & 7) << 4;
    c.aRow  = (uint32_t)(wm * 32 + (lane & 15)) * 128;
    c.aHalf = (uint32_t)(lane >> 4);
    c.bRow  = (uint32_t)(wn * 64 + (lane & 7) + ((lane >> 4) << 3)) * 128;
    c.bHalf = (uint32_t)((lane >> 3) & 1);
    return c;
}

__device__ __forceinline__ void mma_slab(float acc[2][8][4], uint32_t a_base, uint32_t b_base,
                                         const WarpCtx& c) {
#pragma unroll
    for (int q = 0; q < 4; ++q) {
        uint32_t aChunk = ((2 * q + c.aHalf) << 4) ^ c.swb;
        uint32_t bChunk = ((2 * q + c.bHalf) << 4) ^ c.swb;
        uint32_t af[2][4];
#pragma unroll
        for (int i = 0; i < 2; ++i) {
            uint32_t ao = c.aRow + (uint32_t)i * 2048 + aChunk;
            ldsm4(af[i][0], af[i][1], af[i][2], af[i][3], a_base + ao);
        }
        uint32_t bf[4][4];
#pragma unroll
        for (int p = 0; p < 4; ++p) {
            uint32_t bo = c.bRow + (uint32_t)p * 2048 + bChunk;
            ldsm4(bf[p][0], bf[p][1], bf[p][2], bf[p][3], b_base + bo);
        }
#pragma unroll
        for (int i = 0; i < 2; ++i)
#pragma unroll
            for (int g = 0; g < 8; ++g) {
                mma16816(acc[i][g], af[i],
                         bf[g >> 1][(g & 1) * 2], bf[g >> 1][(g & 1) * 2 + 1]);
            }
    }
}

// ---------------- per-step GEMM: v = [h | attn] @ [Wh; Wattn]^T  (K=2048) -------
#define NKT_S 16   // 16 stages x K128
__global__ __launch_bounds__(256, 1) void gemm_step() {
    extern __shared__ char dynsmem[];
    uint32_t sb = smem_u32(dynsmem);
    const int tid = threadIdx.x;
    const int wid = tid >> 5, lane = tid & 31;
    const WarpCtx wc = warp_ctx(wid & 3, wid >> 2, lane);
    const int m0 = blockIdx.y * 128;
    const int n0 = blockIdx.x * 128;

    float acc[2][8][4];
#pragma unroll
    for (int i = 0; i < 2; ++i)
#pragma unroll
        for (int g = 0; g < 8; ++g)
#pragma unroll
            for (int r = 0; r < 4; ++r) acc[i][g][r] = 0.0f;

    auto load_tile = [&](int kt, int stage) {   // kt indexes K128 chunks
        uint32_t base = sb + stage * STAGE_BYTES;
        const __half* ap = (kt < 8) ? g_hh : g_ah;
        size_t akoff = (size_t)(kt & 7) * 128;
        size_t bkoff = (size_t)kt * 128;
#pragma unroll
        for (int slab = 0; slab < 2; ++slab) {
            uint32_t abase = base + (slab ? A_S1 : A_S0);
            uint32_t bbase = base + (slab ? B_S1 : B_S0);
            size_t ks = (size_t)slab * 64;
#pragma unroll
            for (int i = 0; i < 4; ++i) {
                int cidx = tid + i * 256;
                int row = cidx >> 3, c16 = cidx & 7;
                uint32_t off = row * 128 + c16 * 16;
                uint32_t sw = off ^ ((off >> 3) & 0x70);
                size_t aoff = (size_t)(m0 + row) * HH + akoff + ks + (size_t)c16 * 8;
                size_t boff = (size_t)(n0 + row) * KK + bkoff + ks + (size_t)c16 * 8;
                cp16(abase + sw, ap + aoff);
                cp16(bbase + sw, g_wt + boff);
            }
        }
    };

    load_tile(0, 0); cp_commit();
    load_tile(1, 1); cp_commit();

    for (int kt = 0; kt < NKT_S; ++kt) {
        cp_wait<1>();
        __syncthreads();                 // stage kt ready AND stage (kt+2)%3 free
        if (kt + 2 < NKT_S) load_tile(kt + 2, (kt + 2) % 3);
        cp_commit();
        uint32_t base = sb + (kt % 3) * STAGE_BYTES;
        mma_slab(acc, base + A_S0, base + B_S0, wc);
        mma_slab(acc, base + A_S1, base + B_S1, wc);
    }

#pragma unroll
    for (int i = 0; i < 2; ++i) {
        int row0 = m0 + (wid & 3) * 32 + i * 16 + (lane >> 2);
#pragma unroll
        for (int g = 0; g < 8; ++g) {
            int col = n0 + (wid >> 2) * 64 + g * 8 + (lane & 3) * 2;
            *(__half2*)&g_vh[(size_t)row0 * GG + col] =
                __floats2half2_rn(acc[i][g][0], acc[i][g][1]);
            *(__half2*)&g_vh[(size_t)(row0 + 8) * GG + col] =
                __floats2half2_rn(acc[i][g][2], acc[i][g][3]);
        }
    }
}

// ---------------- chunked GEMM: vx[t][n] = x[n,t] @ Wx^T + b  --------------------
// One chunk = 4 timesteps: M = 2048 rows, m = t*512 + n (t = ci*4 + by/4, n0 = (by&3)*128)
#define NKT_X 8    // 8 stages x K128
__global__ __launch_bounds__(256, 1) void gemm_x_chunk(const float* __restrict__ b, int ci) {
    extern __shared__ char dynsmem[];
    uint32_t sb = smem_u32(dynsmem);
    const int tid = threadIdx.x;
    const int wid = tid >> 5, lane = tid & 31;
    const WarpCtx wc = warp_ctx(wid & 3, wid >> 2, lane);
    const int m0 = ci * 2048 + blockIdx.y * 128;       // global m = t*512 + n
    const int tt = m0 >> 9;                            // timestep of this block
    const int nb = m0 & 511;                           // n offset of row 0
    const int n0 = blockIdx.x * 128;

    float acc[2][8][4];
#pragma unroll
    for (int i = 0; i < 2; ++i)
#pragma unroll
        for (int g = 0; g < 8; ++g)
#pragma unroll
            for (int r = 0; r < 4; ++r) acc[i][g][r] = 0.0f;

    auto load_tile = [&](int kt, int stage) {
        uint32_t base = sb + stage * STAGE_BYTES;
        size_t akoff = (size_t)kt * 128;
        size_t bkoff = 2048 + (size_t)kt * 128;
#pragma unroll
        for (int slab = 0; slab < 2; ++slab) {
            uint32_t abase = base + (slab ? A_S1 : A_S0);
            uint32_t bbase = base + (slab ? B_S1 : B_S0);
            size_t ks = (size_t)slab * 64;
#pragma unroll
            for (int i = 0; i < 4; ++i) {
                int cidx = tid + i * 256;
                int row = cidx >> 3, c16 = cidx & 7;
                uint32_t off = row * 128 + c16 * 16;
                uint32_t sw = off ^ ((off >> 3) & 0x70);
                size_t aoff = ((size_t)(nb + row) * TT + tt) * DD + akoff + ks + (size_t)c16 * 8;
                size_t boff = (size_t)(n0 + row) * KK + bkoff + ks + (size_t)c16 * 8;
                cp16(abase + sw, g_xh + aoff);
                cp16(bbase + sw, g_wt + boff);
            }
        }
    };

    load_tile(0, 0); cp_commit();
    load_tile(1, 1); cp_commit();

    for (int kt = 0; kt < NKT_X; ++kt) {
        cp_wait<1>();
        __syncthreads();
        if (kt + 2 < NKT_X) load_tile(kt + 2, (kt + 2) % 3);
        cp_commit();
        uint32_t base = sb + (kt % 3) * STAGE_BYTES;
        mma_slab(acc, base + A_S0, base + B_S0, wc);
        mma_slab(acc, base + A_S1, base + B_S1, wc);
    }

#pragma unroll
    for (int i = 0; i < 2; ++i) {
        int row0 = m0 + (wid & 3) * 32 + i * 16 + (lane >> 2);
#pragma unroll
        for (int g = 0; g < 8; ++g) {
            int col = n0 + (wid >> 2) * 64 + g * 8 + (lane & 3) * 2;
            float2 bb = *(const float2*)&b[col];
            *(__half2*)&g_vxh[(size_t)row0 * GG + col] =
                __floats2half2_rn(acc[i][g][0] + bb.x, acc[i][g][1] + bb.y);
            *(__half2*)&g_vxh[(size_t)(row0 + 8) * GG + col] =
                __floats2half2_rn(acc[i][g][2] + bb.x, acc[i][g][3] + bb.y);
        }
    }
}

// ---------------- gates + state update + output write (2 j per thread) ---------
__global__ void gate_kernel(float* __restrict__ out, int t) {
    int idx2 = blockIdx.x * 256 + threadIdx.x;       // pair index
    int n = idx2 >> 9;
    int jj = (idx2 & 511) * 2;
    const __half* vr  = g_vh  + (size_t)n * GG;
    const __half* vxr = g_vxh + ((size_t)t * NN + n) * GG;   // [t][n][4H]

    float2 vi2 = __half22float2(*(const __half2*)&vr[jj]);
    float2 vf2 = __half22float2(*(const __half2*)&vr[jj + 1024]);
    float2 vo2 = __half22float2(*(const __half2*)&vr[jj + 2048]);
    float2 vg2 = __half22float2(*(const __half2*)&vr[jj + 3072]);
    float2 xi2 = __half22float2(*(const __half2*)&vxr[jj]);
    float2 xf2 = __half22float2(*(const __half2*)&vxr[jj + 1024]);
    float2 xo2 = __half22float2(*(const __half2*)&vxr[jj + 2048]);
    float2 xg2 = __half22float2(*(const __half2*)&vxr[jj + 3072]);

    size_t idx = (size_t)n * HH + jj;
    float2 c2 = *(const float2*)&g_c[idx];
    float h01[2], c01[2];
#pragma unroll
    for (int u = 0; u < 2; ++u) {
        float vi = (u ? vi2.y + xi2.y : vi2.x + xi2.x);
        float vf = (u ? vf2.y + xf2.y : vf2.x + xf2.x);
        float vo = (u ? vo2.y + xo2.y : vo2.x + xo2.x);
        float vg = (u ? vg2.y + xg2.y : vg2.x + xg2.x);
        float ig = 1.0f / (1.0f + expf(-vi));
        float fg = 1.0f / (1.0f + expf(-vf));
        float og = 1.0f / (1.0f + expf(-vo));
        float gg = tanhf(vg);
        float c = fg * (u ? c2.y : c2.x) + ig * gg;
        c01[u] = c;
        h01[u] = og * tanhf(c);
    }
    *(float2*)&g_c[idx] = make_float2(c01[0], c01[1]);
    *(__half2*)&g_hh[idx] = __floats2half2_rn(h01[0], h01[1]);
    *(float2*)&out[(size_t)n * (TT * HH) + (size_t)t * HH + jj] = make_float2(h01[0], h01[1]);
}

// ---------------- launch ---------------------------------------------------------
extern "C" void kernel_launch(void* const* d_in, const int* in_sizes, int n_in,
                              void* d_out, int out_size) {
    const float* x     = (const float*)d_in[0];   // (N, T, D)
    const float* A     = (const float*)d_in[1];   // (N, H, 4, 4)
    const float* Wx    = (const float*)d_in[2];   // (D, 4H)
    const float* Wh    = (const float*)d_in[3];   // (H, 4H)
    const float* Wattn = (const float*)d_in[4];   // (H, 4H)
    const float* b     = (const float*)d_in[5];   // (4H,)
    float* out = (float*)d_out;                   // (N, T, H)

    cudaFuncSetAttribute(gemm_step,    cudaFuncAttributeMaxDynamicSharedMemorySize, GEMM_SMEM);
    cudaFuncSetAttribute(gemm_x_chunk, cudaFuncAttributeMaxDynamicSharedMemorySize, GEMM_SMEM);

    // kernel_launch runs exactly twice (correctness + capture); create fresh
    // stream/events per call — host-side only, no device allocation.
    cudaStream_t s2;
    cudaStreamCreateWithFlags(&s2, cudaStreamNonBlocking);
    cudaEvent_t evFork;
    cudaEventCreateWithFlags(&evFork, cudaEventDisableTiming);
    cudaEvent_t evChunk[8];
    for (int i = 0; i < 8; ++i) cudaEventCreateWithFlags(&evChunk[i], cudaEventDisableTiming);

    prep_w<<<dim3(KK / 32, GG / 32), dim3(32, 8)>>>(Wx, Wh, Wattn);
    cvt_x<<<(NN * TT * DD) / 1024, 256>>>(x);
    cvt_A<<<(NN * HH * 16) / 1024, 256>>>(A);
    init_kernel<<<(NN * HH) / 256, 256>>>(A);

    // fork: gemm_x chunks on s2, overlapping with the recurrent loop
    cudaEventRecord(evFork, 0);
    cudaStreamWaitEvent(s2, evFork, 0);
    for (int ci = 0; ci < 8; ++ci) {
        gemm_x_chunk<<<dim3(GG / 128, 16), 256, GEMM_SMEM, s2>>>(b, ci);
        cudaEventRecord(evChunk[ci], s2);
    }

    for (int t = 0; t < TT; ++t) {
        attn_kernel<<<NN, 256>>>();
        gemm_step<<<dim3(GG / 128, NN / 128), 256, GEMM_SMEM>>>();
        if ((t & 3) == 0) cudaStreamWaitEvent(0, evChunk[t >> 2], 0);   // join chunk t/4
        gate_kernel<<<(NN * HH) / 512, 256>>>(out, t);
    }

    // events/stream are leaked intentionally (2 calls total); destroying a
    // capturing-referenced stream mid-capture is the riskier path.
    for (int i = 0; i < 8; ++i) cudaEventDestroy(evChunk[i]);
    cudaEventDestroy(evFork);
    cudaStreamDestroy(s2);
}